// round 10
// baseline (speedup 1.0000x reference)
#include <cuda_runtime.h>
#include <cstdint>

// ---------------- geometry ----------------
#define T_DIM   4096
#define D_DIM   6144
#define NT0     3072
#define TDM     1024

// ---------------- tiling ------------------
#define KCH     128                  // s8 K per chunk (128B row)
#define NZ      4                    // K splits
#define KSPLIT  (D_DIM/NZ)           // 1536 elems (=bytes)
#define NCHUNK  (KSPLIT/KCH)         // 12 chunks per K-quarter
#define NST     3                    // pipeline stages
#define TILE_B  16384                // 128 rows x 128 B
#define STAGE_B (2*TILE_B)           // A(shift) + B(base)
#define SMEM_DYN (NST*STAGE_B)       // 98304
#define NN0     24
#define NQQ     9
#define NTILE   (NN0*NQQ)            // 216
#define QSCALE  32.0f                // int8 quant scale; C scaled by 1024

typedef unsigned int u32;

// ---------------- scratch (device globals) --------------
__device__ unsigned char g_x8[(size_t)T_DIM * D_DIM];    // 25 MB s8 copy
__device__ float g_S2[T_DIM];
__device__ float g_diag[NZ * NTILE * 256];

// ---------------- PTX helpers ----------------
__device__ __forceinline__ u32 smem_u32(const void* p) {
    u32 a;
    asm("{ .reg .u64 t; cvta.to.shared.u64 t, %1; cvt.u32.u64 %0, t; }"
        : "=r"(a) : "l"(p));
    return a;
}
#define CP_COMMIT()  asm volatile("cp.async.commit_group;" ::: "memory")
#define CP_WAIT(n)   asm volatile("cp.async.wait_group %0;" :: "n"(n) : "memory")

#define LDSM4(r, addr) \
    asm volatile("ldmatrix.sync.aligned.m8n8.x4.shared.b16 {%0,%1,%2,%3}, [%4];" \
        : "=r"((r)[0]), "=r"((r)[1]), "=r"((r)[2]), "=r"((r)[3]) : "r"(addr))

#define MMAS8(c, a, b0, b1) \
    asm volatile("mma.sync.aligned.m16n8k32.row.col.s32.s8.s8.s32 " \
        "{%0,%1,%2,%3}, {%4,%5,%6,%7}, {%8,%9}, {%0,%1,%2,%3};" \
        : "+r"((c)[0]), "+r"((c)[1]), "+r"((c)[2]), "+r"((c)[3]) \
        : "r"((a)[0]), "r"((a)[1]), "r"((a)[2]), "r"((a)[3]), "r"(b0), "r"(b1))

// ---------------------------------------------------------------------------
// Kernel 1: fp32 -> s8 quantize (x*32, rni, clamp) + exact per-row sum sq
// ---------------------------------------------------------------------------
__device__ __forceinline__ int q8(float v) {
    return __float2int_rn(fminf(fmaxf(v * QSCALE, -127.f), 127.f));
}

__global__ void __launch_bounds__(256) s2cvt_kernel(const float* __restrict__ x) {
    int t = blockIdx.x;
    const float4* row = (const float4*)(x + (size_t)t * D_DIM);
    uint2* orow = (uint2*)(g_x8 + (size_t)t * D_DIM);
    float s = 0.f;
    for (int j = threadIdx.x; j < D_DIM / 8; j += 256) {
        float4 v0 = row[2 * j];
        float4 v1 = row[2 * j + 1];
        s += v0.x * v0.x + v0.y * v0.y + v0.z * v0.z + v0.w * v0.w;
        s += v1.x * v1.x + v1.y * v1.y + v1.z * v1.z + v1.w * v1.w;
        uint2 w;
        w.x = (u32)(q8(v0.x) & 0xFF)        | ((u32)(q8(v0.y) & 0xFF) << 8) |
              ((u32)(q8(v0.z) & 0xFF) << 16) | ((u32)(q8(v0.w) & 0xFF) << 24);
        w.y = (u32)(q8(v1.x) & 0xFF)        | ((u32)(q8(v1.y) & 0xFF) << 8) |
              ((u32)(q8(v1.z) & 0xFF) << 16) | ((u32)(q8(v1.w) & 0xFF) << 24);
        orow[j] = w;
    }
    __shared__ float red[256];
    red[threadIdx.x] = s;
    __syncthreads();
    for (int o = 128; o; o >>= 1) {
        if (threadIdx.x < o) red[threadIdx.x] += red[threadIdx.x + o];
        __syncthreads();
    }
    if (threadIdx.x == 0) g_S2[t] = red[0];
}

// ---------------------------------------------------------------------------
// Kernel 2: banded Gram matrix via mma.sync s8 (IMMA), exact s32 accumulate.
// CTA (n0, qq, z): tile G[r][c] = <xq[(n0+qq)*128+r], xq[n0*128+c]> over
// K-quarter z. 8 warps, each 64x32 output, register accumulators.
// ---------------------------------------------------------------------------
__device__ __forceinline__ void load_chunk(u32 stage, int kbase,
                                           int brow, int arow, int tid) {
    const unsigned char* xp = g_x8 + kbase;
#pragma unroll
    for (int it = 0; it < 8; it++) {
        int p = tid + it * 256;
        int t = p >> 10;                  // 0 = A (shift rows), 1 = B (base)
        int r = (p >> 3) & 127;
        int u = p & 7;                    // 16B unit within 128B row
        int grow = (t ? brow : arow) + r;
        const void* src = xp + (size_t)grow * D_DIM + (u << 4);
        u32 dst = stage + (t << 14) +
                  (((u32)(r * 128 + u * 16)) ^ (((u32)(r & 7)) << 4));
        asm volatile("cp.async.cg.shared.global [%0], [%1], 16;"
                     :: "r"(dst), "l"(src) : "memory");
    }
}

__global__ void __launch_bounds__(256, 2) corr_kernel() {
    extern __shared__ __align__(1024) char smem[];
    const u32 sb = smem_u32(smem);
    const int tid = threadIdx.x, l = tid & 31, wid = tid >> 5;
    const int warp_m = wid >> 2, warp_n = wid & 3;
    const int n0 = blockIdx.x, qq = blockIdx.y, z = blockIdx.z;
    const int brow = n0 << 7;
    const int arow = (n0 + qq) << 7;
    const int kbase = z * KSPLIT;         // bytes

    int c[4][4][4];
#pragma unroll
    for (int i = 0; i < 4; i++)
#pragma unroll
        for (int j = 0; j < 4; j++)
#pragma unroll
            for (int k = 0; k < 4; k++) c[i][j][k] = 0;

    // Unswizzled per-lane base offsets; swizzle XOR applied LAST at each
    // ldmatrix (swz depends only on row&7, invariant under all offsets).
    const int a_row = warp_m * 64 + ((l >> 3) & 1) * 8 + (l & 7);
    const u32 a_off = (u32)(a_row * 128 + (l >> 4) * 16);
    const u32 a_swz = ((u32)(a_row & 7)) << 4;
    const int b_row = warp_n * 32 + (l & 7);
    const u32 b_off = (u32)(b_row * 128 + (l >> 3) * 16);
    const u32 b_swz = ((u32)(b_row & 7)) << 4;

    // Prologue: 2 stages in flight
    for (int s = 0; s < 2; s++) {
        load_chunk(sb + s * STAGE_B, kbase + s * KCH, brow, arow, tid);
        CP_COMMIT();
    }

    int sidx = 0;
    for (int ch = 0; ch < NCHUNK; ch++) {
        CP_WAIT(1);
        __syncthreads();
        const u32 Ab = sb + sidx * STAGE_B + a_off;
        const u32 Bb = sb + sidx * STAGE_B + TILE_B + b_off;
#pragma unroll
        for (int kd = 0; kd < 2; kd++) {          // 64-byte k halves
            u32 bq[4][4];
#pragma unroll
            for (int ni = 0; ni < 4; ni++)
                LDSM4(bq[ni], (Bb + ni * 1024 + kd * 64) ^ b_swz);
#pragma unroll
            for (int h = 0; h < 2; h++) {         // 32-byte k steps
                u32 aq[4][4];
#pragma unroll
                for (int mi = 0; mi < 4; mi++)
                    LDSM4(aq[mi], (Ab + mi * 2048 + (kd * 2 + h) * 32) ^ a_swz);
#pragma unroll
                for (int mi = 0; mi < 4; mi++)
#pragma unroll
                    for (int ni = 0; ni < 4; ni++)
                        MMAS8(c[mi][ni], aq[mi],
                              bq[ni][2 * h], bq[ni][2 * h + 1]);
            }
        }
        int cn = ch + 2;
        if (cn < NCHUNK) {
            int sn = sidx + 2; if (sn >= NST) sn -= NST;
            load_chunk(sb + sn * STAGE_B, kbase + cn * KCH, brow, arow, tid);
        }
        CP_COMMIT();
        if (++sidx == NST) sidx = 0;
    }

    // Epilogue: s32 regs -> smem G as float (exact, |G| < 2^24) -> diag sums
    __syncthreads();
    float* G = (float*)smem;
#pragma unroll
    for (int mi = 0; mi < 4; mi++)
#pragma unroll
        for (int ni = 0; ni < 4; ni++) {
            int r0 = warp_m * 64 + mi * 16 + (l >> 2);
            int c0 = warp_n * 32 + ni * 8 + ((l & 3) << 1);
            G[r0 * 129 + c0]           = (float)c[mi][ni][0];
            G[r0 * 129 + c0 + 1]       = (float)c[mi][ni][1];
            G[(r0 + 8) * 129 + c0]     = (float)c[mi][ni][2];
            G[(r0 + 8) * 129 + c0 + 1] = (float)c[mi][ni][3];
        }
    __syncthreads();

    if (tid < 255) {
        int d = tid - 127;              // td = 128*qq + d
        float s = 0.f;
        for (int rr = 0; rr < 128; rr++) {
            int cc = rr - d;
            if ((unsigned)cc < 128u) s += G[rr * 129 + cc];
        }
        g_diag[((size_t)(z * NTILE + n0 * NQQ + qq)) * 256 + tid] = s;
    }
}

// ---------------------------------------------------------------------------
// Kernel 3: finalize. msd[td] = (A[td] + A[0] - 2*C[td]/1024) / (NT0*D)
// ---------------------------------------------------------------------------
__global__ void __launch_bounds__(256) finalize_kernel(float* __restrict__ out) {
    const int td = blockIdx.x, tid = threadIdx.x;
    const int qq = td >> 7, d1 = td & 127;
    const double INV_QS2 = 1.0 / ((double)QSCALE * (double)QSCALE);

    double c = 0.0;
    if (tid < NN0 * NZ) {
        int n = tid >> 2, zz = tid & 3;
        c = (double)g_diag[((size_t)(zz * NTILE + n * NQQ + qq)) * 256 + 127 + d1];
        if (d1)
            c += (double)g_diag[((size_t)(zz * NTILE + n * NQQ + qq + 1)) * 256 + d1 - 1];
        c *= INV_QS2;
    }

    double a = 0.0, a0 = 0.0;
    for (int j = tid; j < NT0; j += 256) {
        a  += (double)g_S2[td + j];
        a0 += (double)g_S2[j];
    }

    double part = a + a0 - 2.0 * c;
    __shared__ double red[256];
    red[tid] = part;
    __syncthreads();
    for (int o = 128; o; o >>= 1) {
        if (tid < o) red[tid] += red[tid + o];
        __syncthreads();
    }
    if (tid == 0) {
        const double invN = 1.0 / ((double)NT0 * (double)D_DIM);
        out[td] = (td == 0) ? 0.0f : (float)(red[0] * invN);
    }
}

// ---------------------------------------------------------------------------
extern "C" void kernel_launch(void* const* d_in, const int* in_sizes, int n_in,
                              void* d_out, int out_size) {
    (void)in_sizes; (void)n_in; (void)out_size;
    const float* x = (const float*)d_in[0];
    float* out = (float*)d_out;

    static bool attr_set = false;
    if (!attr_set) {
        cudaFuncSetAttribute(corr_kernel,
                             cudaFuncAttributeMaxDynamicSharedMemorySize,
                             SMEM_DYN);
        attr_set = true;
    }

    s2cvt_kernel<<<T_DIM, 256>>>(x);
    corr_kernel<<<dim3(NN0, NQQ, NZ), 256, SMEM_DYN>>>();
    finalize_kernel<<<TDM, 256>>>(out);
}

// round 11
// speedup vs baseline: 2.1233x; 2.1233x over previous
#include <cuda_runtime.h>
#include <cuda_fp16.h>
#include <cstdint>

// ---------------- geometry ----------------
#define T_DIM   4096
#define D_DIM   6144
#define NT0     3072
#define TDM     1024

// ---------------- tiling ------------------
#define KCH     64                   // f16 K per chunk (128B row)
#define NZ      4                    // K splits
#define KSPLIT  (D_DIM/NZ)           // 1536
#define NCHUNK  (KSPLIT/KCH)         // 24 chunks per K-quarter
#define NST     3                    // pipeline stages
#define TILE_B  16384                // 128 rows x 128 B
#define STAGE_B (2*TILE_B)           // A(shift) + B(base)
#define SMEM_DYN (NST*STAGE_B)       // 98304
#define NN0     24
#define NQQ     9
#define NTILE   (NN0*NQQ)            // 216

typedef unsigned int u32;

// ---------------- scratch (device globals) --------------
__device__ __half g_xh[(size_t)T_DIM * D_DIM];           // 48 MB fp16 copy
__device__ float g_S2[T_DIM];
__device__ float g_diag[NZ * NTILE * 256];

// ---------------- PTX helpers ----------------
__device__ __forceinline__ u32 smem_u32(const void* p) {
    u32 a;
    asm("{ .reg .u64 t; cvta.to.shared.u64 t, %1; cvt.u32.u64 %0, t; }"
        : "=r"(a) : "l"(p));
    return a;
}
#define CP_COMMIT()  asm volatile("cp.async.commit_group;" ::: "memory")
#define CP_WAIT(n)   asm volatile("cp.async.wait_group %0;" :: "n"(n) : "memory")

#define LDSM4(r, addr) \
    asm volatile("ldmatrix.sync.aligned.m8n8.x4.shared.b16 {%0,%1,%2,%3}, [%4];" \
        : "=r"((r)[0]), "=r"((r)[1]), "=r"((r)[2]), "=r"((r)[3]) : "r"(addr))

// fp16 inputs, fp16 accumulate (2x rate target), C = two b32 regs (f16x2)
#define MMAF16(c, a, b0, b1) \
    asm volatile("mma.sync.aligned.m16n8k16.row.col.f16.f16.f16.f16 " \
        "{%0,%1}, {%2,%3,%4,%5}, {%6,%7}, {%0,%1};" \
        : "+r"((c)[0]), "+r"((c)[1]) \
        : "r"((a)[0]), "r"((a)[1]), "r"((a)[2]), "r"((a)[3]), "r"(b0), "r"(b1))

// ---------------------------------------------------------------------------
// Kernel 1: fp32 -> fp16 convert + exact per-row sum of squares
// ---------------------------------------------------------------------------
__global__ void __launch_bounds__(256) s2cvt_kernel(const float* __restrict__ x) {
    int t = blockIdx.x;
    const float4* row = (const float4*)(x + (size_t)t * D_DIM);
    uint4* orow = (uint4*)(g_xh + (size_t)t * D_DIM);
    float s = 0.f;
    for (int j = threadIdx.x; j < D_DIM / 8; j += 256) {
        float4 v0 = row[2 * j];
        float4 v1 = row[2 * j + 1];
        s += v0.x * v0.x + v0.y * v0.y + v0.z * v0.z + v0.w * v0.w;
        s += v1.x * v1.x + v1.y * v1.y + v1.z * v1.z + v1.w * v1.w;
        __half2 p0 = __float22half2_rn(make_float2(v0.x, v0.y));
        __half2 p1 = __float22half2_rn(make_float2(v0.z, v0.w));
        __half2 p2 = __float22half2_rn(make_float2(v1.x, v1.y));
        __half2 p3 = __float22half2_rn(make_float2(v1.z, v1.w));
        uint4 w;
        w.x = *(u32*)&p0; w.y = *(u32*)&p1;
        w.z = *(u32*)&p2; w.w = *(u32*)&p3;
        orow[j] = w;
    }
    __shared__ float red[256];
    red[threadIdx.x] = s;
    __syncthreads();
    for (int o = 128; o; o >>= 1) {
        if (threadIdx.x < o) red[threadIdx.x] += red[threadIdx.x + o];
        __syncthreads();
    }
    if (threadIdx.x == 0) g_S2[t] = red[0];
}

// ---------------------------------------------------------------------------
// Kernel 2: banded Gram matrix via mma.sync f16 (HMMA, f16 accumulate).
// CTA (n0, qq, z): tile G[r][c] = <x[(n0+qq)*128+r], x[n0*128+c]> over
// K-quarter z. 8 warps, each 64x32 output. Warps whose whole region maps
// to unused td (qq=0 upper-right, qq=8 lower-left) skip all tensor work.
// ---------------------------------------------------------------------------
__device__ __forceinline__ void load_chunk(u32 stage, int kbase,
                                           int brow, int arow, int tid) {
    const __half* xp = g_xh + kbase;
#pragma unroll
    for (int it = 0; it < 8; it++) {
        int p = tid + it * 256;
        int t = p >> 10;                  // 0 = A (shift rows), 1 = B (base)
        int r = (p >> 3) & 127;
        int u = p & 7;                    // 16B unit within 128B row
        int grow = (t ? brow : arow) + r;
        const void* src = xp + (size_t)grow * D_DIM + (u << 3);
        u32 dst = stage + (t << 14) +
                  (((u32)(r * 128 + u * 16)) ^ (((u32)(r & 7)) << 4));
        asm volatile("cp.async.cg.shared.global [%0], [%1], 16;"
                     :: "r"(dst), "l"(src) : "memory");
    }
}

__global__ void __launch_bounds__(256, 2) corr_kernel() {
    extern __shared__ __align__(1024) char smem[];
    const u32 sb = smem_u32(smem);
    const int tid = threadIdx.x, l = tid & 31, wid = tid >> 5;
    const int warp_m = wid >> 2, warp_n = wid & 3;
    const int n0 = blockIdx.x, qq = blockIdx.y, z = blockIdx.z;
    const int brow = n0 << 7;
    const int arow = (n0 + qq) << 7;
    const int kbase = z * KSPLIT;

    // Warp-region td usefulness: qq=0 needs d>=1 (drop r<64 & c>=64 warps);
    // qq=8 needs d<=-1 (drop r>=64 & c<64 warps).
    bool warp_active = true;
    if (qq == 0 && warp_m == 0 && warp_n >= 2) warp_active = false;
    if (qq == 8 && warp_m == 1 && warp_n < 2)  warp_active = false;

    u32 c[4][4][2];
#pragma unroll
    for (int i = 0; i < 4; i++)
#pragma unroll
        for (int j = 0; j < 4; j++)
            c[i][j][0] = c[i][j][1] = 0u;   // f16x2 zeros

    // Unswizzled per-lane base offsets; swizzle XOR applied LAST at each
    // ldmatrix (swz depends only on row&7, invariant under all offsets).
    const int a_row = warp_m * 64 + ((l >> 3) & 1) * 8 + (l & 7);
    const u32 a_off = (u32)(a_row * 128 + (l >> 4) * 16);
    const u32 a_swz = ((u32)(a_row & 7)) << 4;
    const int b_row = warp_n * 32 + (l & 7);
    const u32 b_off = (u32)(b_row * 128 + (l >> 3) * 16);
    const u32 b_swz = ((u32)(b_row & 7)) << 4;

    // Prologue: 2 stages in flight
    for (int s = 0; s < 2; s++) {
        load_chunk(sb + s * STAGE_B, kbase + s * KCH, brow, arow, tid);
        CP_COMMIT();
    }

    int sidx = 0;
    for (int ch = 0; ch < NCHUNK; ch++) {
        CP_WAIT(1);
        __syncthreads();
        if (warp_active) {
            const u32 Ab = sb + sidx * STAGE_B + a_off;
            const u32 Bb = sb + sidx * STAGE_B + TILE_B + b_off;
#pragma unroll
            for (int kd = 0; kd < 2; kd++) {
                u32 bq[4][4];
#pragma unroll
                for (int ni = 0; ni < 4; ni++)
                    LDSM4(bq[ni], (Bb + ni * 1024 + kd * 64) ^ b_swz);
#pragma unroll
                for (int h = 0; h < 2; h++) {
                    u32 aq[4][4];
#pragma unroll
                    for (int mi = 0; mi < 4; mi++)
                        LDSM4(aq[mi], (Ab + mi * 2048 + (kd * 2 + h) * 32) ^ a_swz);
#pragma unroll
                    for (int mi = 0; mi < 4; mi++)
#pragma unroll
                        for (int ni = 0; ni < 4; ni++)
                            MMAF16(c[mi][ni], aq[mi],
                                   bq[ni][2 * h], bq[ni][2 * h + 1]);
                }
            }
        }
        int cn = ch + 2;
        if (cn < NCHUNK) {
            int sn = sidx + 2; if (sn >= NST) sn -= NST;
            load_chunk(sb + sn * STAGE_B, kbase + cn * KCH, brow, arow, tid);
        }
        CP_COMMIT();
        if (++sidx == NST) sidx = 0;
    }

    // Epilogue: f16x2 regs -> float -> smem G (pitch 129) -> diagonal sums
    __syncthreads();
    float* G = (float*)smem;
#pragma unroll
    for (int mi = 0; mi < 4; mi++)
#pragma unroll
        for (int ni = 0; ni < 4; ni++) {
            int r0 = warp_m * 64 + mi * 16 + (l >> 2);
            int c0 = warp_n * 32 + ni * 8 + ((l & 3) << 1);
            float2 f0 = __half22float2(*(__half2*)&c[mi][ni][0]);
            float2 f1 = __half22float2(*(__half2*)&c[mi][ni][1]);
            G[r0 * 129 + c0]           = f0.x;
            G[r0 * 129 + c0 + 1]       = f0.y;
            G[(r0 + 8) * 129 + c0]     = f1.x;
            G[(r0 + 8) * 129 + c0 + 1] = f1.y;
        }
    __syncthreads();

    if (tid < 255) {
        int d = tid - 127;              // td = 128*qq + d
        float s = 0.f;
        for (int rr = 0; rr < 128; rr++) {
            int cc = rr - d;
            if ((unsigned)cc < 128u) s += G[rr * 129 + cc];
        }
        g_diag[((size_t)(z * NTILE + n0 * NQQ + qq)) * 256 + tid] = s;
    }
}

// ---------------------------------------------------------------------------
// Kernel 3: finalize. msd[td] = (A[td] + A[0] - 2*C[td]) / (NT0*D)
// ---------------------------------------------------------------------------
__global__ void __launch_bounds__(256) finalize_kernel(float* __restrict__ out) {
    const int td = blockIdx.x, tid = threadIdx.x;
    const int qq = td >> 7, d1 = td & 127;

    double c = 0.0;
    if (tid < NN0 * NZ) {
        int n = tid >> 2, zz = tid & 3;
        c = (double)g_diag[((size_t)(zz * NTILE + n * NQQ + qq)) * 256 + 127 + d1];
        if (d1)
            c += (double)g_diag[((size_t)(zz * NTILE + n * NQQ + qq + 1)) * 256 + d1 - 1];
    }

    double a = 0.0, a0 = 0.0;
    for (int j = tid; j < NT0; j += 256) {
        a  += (double)g_S2[td + j];
        a0 += (double)g_S2[j];
    }

    double part = a + a0 - 2.0 * c;
    __shared__ double red[256];
    red[tid] = part;
    __syncthreads();
    for (int o = 128; o; o >>= 1) {
        if (tid < o) red[tid] += red[tid + o];
        __syncthreads();
    }
    if (tid == 0) {
        const double invN = 1.0 / ((double)NT0 * (double)D_DIM);
        out[td] = (td == 0) ? 0.0f : (float)(red[0] * invN);
    }
}

// ---------------------------------------------------------------------------
extern "C" void kernel_launch(void* const* d_in, const int* in_sizes, int n_in,
                              void* d_out, int out_size) {
    (void)in_sizes; (void)n_in; (void)out_size;
    const float* x = (const float*)d_in[0];
    float* out = (float*)d_out;

    static bool attr_set = false;
    if (!attr_set) {
        cudaFuncSetAttribute(corr_kernel,
                             cudaFuncAttributeMaxDynamicSharedMemorySize,
                             SMEM_DYN);
        attr_set = true;
    }

    s2cvt_kernel<<<T_DIM, 256>>>(x);
    corr_kernel<<<dim3(NN0, NQQ, NZ), 256, SMEM_DYN>>>();
    finalize_kernel<<<TDM, 256>>>(out);
}

// round 13
// speedup vs baseline: 2.2603x; 1.0645x over previous
#include <cuda_runtime.h>
#include <cuda_fp16.h>
#include <cstdint>

// ---------------- geometry ----------------
#define T_DIM   4096
#define D_DIM   6144
#define NT0     3072
#define TDM     1024

// ---------------- tiling ------------------
#define KCH     64                   // f16 K per chunk (128B row)
#define NZ      4                    // K splits
#define KSPLIT  (D_DIM/NZ)           // 1536
#define NCHUNK  (KSPLIT/KCH)         // 24 chunks per K-quarter
#define NST     3                    // pipeline stages
#define TILE_B  16384                // 128 rows x 128 B
#define STAGE_B (2*TILE_B)           // A(shift) + B(base)
#define SMEM_DYN (NST*STAGE_B)       // 98304
#define NN0     24
#define NQQ     9
#define NTILE   (NN0*NQQ)            // 216

typedef unsigned int u32;

// ---------------- scratch (device globals) --------------
__device__ __half g_xh[(size_t)T_DIM * D_DIM];           // 48 MB fp16 copy
__device__ float g_S2[T_DIM];
__device__ double g_pref[T_DIM + 1];                     // prefix sums of S2
__device__ float g_diag[NZ * NTILE * 256];

// ---------------- PTX helpers ----------------
__device__ __forceinline__ u32 smem_u32(const void* p) {
    u32 a;
    asm("{ .reg .u64 t; cvta.to.shared.u64 t, %1; cvt.u32.u64 %0, t; }"
        : "=r"(a) : "l"(p));
    return a;
}
#define CP_COMMIT()  asm volatile("cp.async.commit_group;" ::: "memory")
#define CP_WAIT(n)   asm volatile("cp.async.wait_group %0;" :: "n"(n) : "memory")

#define LDSM4(r, addr) \
    asm volatile("ldmatrix.sync.aligned.m8n8.x4.shared.b16 {%0,%1,%2,%3}, [%4];" \
        : "=r"((r)[0]), "=r"((r)[1]), "=r"((r)[2]), "=r"((r)[3]) : "r"(addr))

// fp16 inputs, fp16 accumulate, C = two b32 regs (f16x2)
#define MMAF16(c, a, b0, b1) \
    asm volatile("mma.sync.aligned.m16n8k16.row.col.f16.f16.f16.f16 " \
        "{%0,%1}, {%2,%3,%4,%5}, {%6,%7}, {%0,%1};" \
        : "+r"((c)[0]), "+r"((c)[1]) \
        : "r"((a)[0]), "r"((a)[1]), "r"((a)[2]), "r"((a)[3]), "r"(b0), "r"(b1))

// ---------------------------------------------------------------------------
// Kernel 1: fp32 -> fp16 convert + exact per-row sum of squares.
// Batched loads (6 in flight) for MLP; 16B stores.
// ---------------------------------------------------------------------------
__global__ void __launch_bounds__(256) s2cvt_kernel(const float* __restrict__ x) {
    int t = blockIdx.x;
    const float4* row = (const float4*)(x + (size_t)t * D_DIM);
    uint4* orow = (uint4*)(g_xh + (size_t)t * D_DIM);
    const int tid = threadIdx.x;

    float4 v[6];
#pragma unroll
    for (int i = 0; i < 3; i++) {
        v[2 * i]     = row[2 * tid + 512 * i];
        v[2 * i + 1] = row[2 * tid + 512 * i + 1];
    }
    float s = 0.f;
#pragma unroll
    for (int i = 0; i < 6; i++)
        s += v[i].x * v[i].x + v[i].y * v[i].y + v[i].z * v[i].z + v[i].w * v[i].w;
#pragma unroll
    for (int i = 0; i < 3; i++) {
        __half2 p0 = __float22half2_rn(make_float2(v[2*i].x,   v[2*i].y));
        __half2 p1 = __float22half2_rn(make_float2(v[2*i].z,   v[2*i].w));
        __half2 p2 = __float22half2_rn(make_float2(v[2*i+1].x, v[2*i+1].y));
        __half2 p3 = __float22half2_rn(make_float2(v[2*i+1].z, v[2*i+1].w));
        uint4 w;
        w.x = *(u32*)&p0; w.y = *(u32*)&p1;
        w.z = *(u32*)&p2; w.w = *(u32*)&p3;
        orow[tid + 256 * i] = w;
    }

    __shared__ float red[256];
    red[tid] = s;
    __syncthreads();
    for (int o = 128; o; o >>= 1) {
        if (tid < o) red[tid] += red[tid + o];
        __syncthreads();
    }
    if (tid == 0) g_S2[t] = red[0];
}

// ---------------------------------------------------------------------------
// Kernel 1b: prefix sums of S2 (one block, double precision)
// ---------------------------------------------------------------------------
__global__ void __launch_bounds__(1024) prefix_kernel() {
    __shared__ double sm[1024];
    const int tid = threadIdx.x;
    double v[4], s = 0.0;
#pragma unroll
    for (int i = 0; i < 4; i++) { v[i] = (double)g_S2[4 * tid + i]; s += v[i]; }
    sm[tid] = s;
    __syncthreads();
    for (int off = 1; off < 1024; off <<= 1) {
        double tv = (tid >= off) ? sm[tid - off] : 0.0;
        __syncthreads();
        sm[tid] += tv;
        __syncthreads();
    }
    double run = tid ? sm[tid - 1] : 0.0;
    if (tid == 0) g_pref[0] = 0.0;
#pragma unroll
    for (int i = 0; i < 4; i++) { run += v[i]; g_pref[4 * tid + i + 1] = run; }
}

// ---------------------------------------------------------------------------
// Kernel 2: banded Gram matrix via mma.sync f16 (HMMA, f16 accumulate).
// CTA (n0, qq, z): tile G[r][c] = <x[(n0+qq)*128+r], x[n0*128+c]>.
// Per-warp 16-bit fragment mask skips fragments whose td range is unused
// (qq=0 needs r>c; qq=8 needs c>r).
// ---------------------------------------------------------------------------
__device__ __forceinline__ void load_chunk(u32 stage, int kbase,
                                           int brow, int arow, int tid) {
    const __half* xp = g_xh + kbase;
#pragma unroll
    for (int it = 0; it < 8; it++) {
        int p = tid + it * 256;
        int t = p >> 10;                  // 0 = A (shift rows), 1 = B (base)
        int r = (p >> 3) & 127;
        int u = p & 7;
        int grow = (t ? brow : arow) + r;
        const void* src = xp + (size_t)grow * D_DIM + (u << 3);
        u32 dst = stage + (t << 14) +
                  (((u32)(r * 128 + u * 16)) ^ (((u32)(r & 7)) << 4));
        asm volatile("cp.async.cg.shared.global [%0], [%1], 16;"
                     :: "r"(dst), "l"(src) : "memory");
    }
}

__global__ void __launch_bounds__(256, 2) corr_kernel() {
    extern __shared__ __align__(1024) char smem[];
    const u32 sb = smem_u32(smem);
    const int tid = threadIdx.x, l = tid & 31, wid = tid >> 5;
    const int warp_m = wid >> 2, warp_n = wid & 3;
    const int n0 = blockIdx.x, qq = blockIdx.y, z = blockIdx.z;
    const int brow = n0 << 7;
    const int arow = (n0 + qq) << 7;
    const int kbase = z * KSPLIT;

    // Fragment usefulness mask (bit mi*4+ni). Interior: all 16.
    unsigned mask = 0xFFFFu;
    if (qq == 0 || qq == 8) {
        mask = 0;
#pragma unroll
        for (int mi = 0; mi < 4; mi++)
#pragma unroll
            for (int ni = 0; ni < 4; ni++) {
                int r0 = warp_m * 64 + mi * 16;
                int c0 = warp_n * 32 + ni * 8;
                bool used = (qq == 0) ? (r0 + 15 > c0)   // need some r > c
                                      : (c0 + 7 > r0);   // need some c > r
                if (used) mask |= 1u << (mi * 4 + ni);
            }
    }

    u32 c[4][4][2];
#pragma unroll
    for (int i = 0; i < 4; i++)
#pragma unroll
        for (int j = 0; j < 4; j++)
            c[i][j][0] = c[i][j][1] = 0u;

    const int a_row = warp_m * 64 + ((l >> 3) & 1) * 8 + (l & 7);
    const u32 a_off = (u32)(a_row * 128 + (l >> 4) * 16);
    const u32 a_swz = ((u32)(a_row & 7)) << 4;
    const int b_row = warp_n * 32 + (l & 7);
    const u32 b_off = (u32)(b_row * 128 + (l >> 3) * 16);
    const u32 b_swz = ((u32)(b_row & 7)) << 4;

    for (int s = 0; s < 2; s++) {
        load_chunk(sb + s * STAGE_B, kbase + s * KCH, brow, arow, tid);
        CP_COMMIT();
    }

    int sidx = 0;
    for (int ch = 0; ch < NCHUNK; ch++) {
        CP_WAIT(1);
        __syncthreads();
        if (mask) {
            const u32 Ab = sb + sidx * STAGE_B + a_off;
            const u32 Bb = sb + sidx * STAGE_B + TILE_B + b_off;
#pragma unroll
            for (int kd = 0; kd < 2; kd++) {
                u32 bq[4][4];
#pragma unroll
                for (int ni = 0; ni < 4; ni++)
                    LDSM4(bq[ni], (Bb + ni * 1024 + kd * 64) ^ b_swz);
#pragma unroll
                for (int h = 0; h < 2; h++) {
                    u32 aq[4][4];
#pragma unroll
                    for (int mi = 0; mi < 4; mi++)
                        LDSM4(aq[mi], (Ab + mi * 2048 + (kd * 2 + h) * 32) ^ a_swz);
                    if (mask == 0xFFFFu) {
#pragma unroll
                        for (int mi = 0; mi < 4; mi++)
#pragma unroll
                            for (int ni = 0; ni < 4; ni++)
                                MMAF16(c[mi][ni], aq[mi],
                                       bq[ni][2 * h], bq[ni][2 * h + 1]);
                    } else {
#pragma unroll
                        for (int mi = 0; mi < 4; mi++)
#pragma unroll
                            for (int ni = 0; ni < 4; ni++)
                                if (mask & (1u << (mi * 4 + ni)))
                                    MMAF16(c[mi][ni], aq[mi],
                                           bq[ni][2 * h], bq[ni][2 * h + 1]);
                    }
                }
            }
        }
        int cn = ch + 2;
        if (cn < NCHUNK) {
            int sn = sidx + 2; if (sn >= NST) sn -= NST;
            load_chunk(sb + sn * STAGE_B, kbase + cn * KCH, brow, arow, tid);
        }
        CP_COMMIT();
        if (++sidx == NST) sidx = 0;
    }

    // Epilogue: f16x2 regs -> float -> smem G (pitch 129) -> diagonal sums
    __syncthreads();
    float* G = (float*)smem;
#pragma unroll
    for (int mi = 0; mi < 4; mi++)
#pragma unroll
        for (int ni = 0; ni < 4; ni++) {
            int r0 = warp_m * 64 + mi * 16 + (l >> 2);
            int c0 = warp_n * 32 + ni * 8 + ((l & 3) << 1);
            float2 f0 = __half22float2(*(__half2*)&c[mi][ni][0]);
            float2 f1 = __half22float2(*(__half2*)&c[mi][ni][1]);
            G[r0 * 129 + c0]           = f0.x;
            G[r0 * 129 + c0 + 1]       = f0.y;
            G[(r0 + 8) * 129 + c0]     = f1.x;
            G[(r0 + 8) * 129 + c0 + 1] = f1.y;
        }
    __syncthreads();

    if (tid < 255) {
        int d = tid - 127;              // td = 128*qq + d
        float s = 0.f;
        for (int rr = 0; rr < 128; rr++) {
            int cc = rr - d;
            if ((unsigned)cc < 128u) s += G[rr * 129 + cc];
        }
        g_diag[((size_t)(z * NTILE + n0 * NQQ + qq)) * 256 + tid] = s;
    }
}

// ---------------------------------------------------------------------------
// Kernel 3: finalize. msd[td] = (A[td] + A[0] - 2*C[td]) / (NT0*D)
// A-terms from prefix sums (no bulk S2 re-read).
// ---------------------------------------------------------------------------
__global__ void __launch_bounds__(128) finalize_kernel(float* __restrict__ out) {
    const int td = blockIdx.x, tid = threadIdx.x;
    const int qq = td >> 7, d1 = td & 127;

    double cacc = 0.0;
    if (tid < NN0 * NZ) {
        int n = tid >> 2, zz = tid & 3;
        cacc = (double)g_diag[((size_t)(zz * NTILE + n * NQQ + qq)) * 256 + 127 + d1];
        if (d1)
            cacc += (double)g_diag[((size_t)(zz * NTILE + n * NQQ + qq + 1)) * 256 + d1 - 1];
    }

    __shared__ double red[128];
    red[tid] = cacc;
    __syncthreads();
    for (int o = 64; o; o >>= 1) {
        if (tid < o) red[tid] += red[tid + o];
        __syncthreads();
    }
    if (tid == 0) {
        double a  = g_pref[td + NT0] - g_pref[td];
        double a0 = g_pref[NT0];
        const double invN = 1.0 / ((double)NT0 * (double)D_DIM);
        out[td] = (td == 0) ? 0.0f
                            : (float)((a + a0 - 2.0 * red[0]) * invN);
    }
}

// ---------------------------------------------------------------------------
extern "C" void kernel_launch(void* const* d_in, const int* in_sizes, int n_in,
                              void* d_out, int out_size) {
    (void)in_sizes; (void)n_in; (void)out_size;
    const float* x = (const float*)d_in[0];
    float* out = (float*)d_out;

    static bool attr_set = false;
    if (!attr_set) {
        cudaFuncSetAttribute(corr_kernel,
                             cudaFuncAttributeMaxDynamicSharedMemorySize,
                             SMEM_DYN);
        attr_set = true;
    }

    s2cvt_kernel<<<T_DIM, 256>>>(x);
    prefix_kernel<<<1, 1024>>>();
    corr_kernel<<<dim3(NN0, NQQ, NZ), 256, SMEM_DYN>>>();
    finalize_kernel<<<TDM, 128>>>(out);
}

// round 14
// speedup vs baseline: 2.2672x; 1.0030x over previous
#include <cuda_runtime.h>
#include <cuda_fp16.h>
#include <cstdint>

// ---------------- geometry ----------------
#define T_DIM   4096
#define D_DIM   6144
#define NT0     3072
#define TDM     1024

// ---------------- tiling ------------------
#define KCH     64                   // f16 K per chunk (128B row)
#define NZ      4                    // K splits
#define KSPLIT  (D_DIM/NZ)           // 1536
#define NCHUNK  (KSPLIT/KCH)         // 24 chunks per K-quarter
#define NST     3                    // pipeline stages
#define TILE_B  16384                // 128 rows x 128 B
#define STAGE_B (2*TILE_B)           // A(shift) + B(base)
#define SMEM_DYN (NST*STAGE_B)       // 98304
#define NN0     24
#define NQQ     9
#define NTILE   (NN0*NQQ)            // 216

typedef unsigned int u32;

// ---------------- scratch (device globals) --------------
__device__ __half g_xh[(size_t)T_DIM * D_DIM];           // 48 MB fp16 copy
__device__ float g_S2[T_DIM];
__device__ double g_pref[T_DIM + 1];                     // prefix sums of S2
__device__ float g_diag[NZ * NTILE * 256];

// ---------------- PTX helpers ----------------
__device__ __forceinline__ u32 smem_u32(const void* p) {
    u32 a;
    asm("{ .reg .u64 t; cvta.to.shared.u64 t, %1; cvt.u32.u64 %0, t; }"
        : "=r"(a) : "l"(p));
    return a;
}
#define CP_COMMIT()  asm volatile("cp.async.commit_group;" ::: "memory")
#define CP_WAIT(n)   asm volatile("cp.async.wait_group %0;" :: "n"(n) : "memory")

#define LDSM4(r, addr) \
    asm volatile("ldmatrix.sync.aligned.m8n8.x4.shared.b16 {%0,%1,%2,%3}, [%4];" \
        : "=r"((r)[0]), "=r"((r)[1]), "=r"((r)[2]), "=r"((r)[3]) : "r"(addr))

// fp16 inputs, fp16 accumulate, C = two b32 regs (f16x2)
#define MMAF16(c, a, b0, b1) \
    asm volatile("mma.sync.aligned.m16n8k16.row.col.f16.f16.f16.f16 " \
        "{%0,%1}, {%2,%3,%4,%5}, {%6,%7}, {%0,%1};" \
        : "+r"((c)[0]), "+r"((c)[1]) \
        : "r"((a)[0]), "r"((a)[1]), "r"((a)[2]), "r"((a)[3]), "r"(b0), "r"(b1))

// ---------------------------------------------------------------------------
// Kernel 1: fp32 -> fp16 convert + exact per-row sum of squares.
// ---------------------------------------------------------------------------
__global__ void __launch_bounds__(256) s2cvt_kernel(const float* __restrict__ x) {
    int t = blockIdx.x;
    const float4* row = (const float4*)(x + (size_t)t * D_DIM);
    uint4* orow = (uint4*)(g_xh + (size_t)t * D_DIM);
    const int tid = threadIdx.x;

    float4 v[6];
#pragma unroll
    for (int i = 0; i < 3; i++) {
        v[2 * i]     = row[2 * tid + 512 * i];
        v[2 * i + 1] = row[2 * tid + 512 * i + 1];
    }
    float s = 0.f;
#pragma unroll
    for (int i = 0; i < 6; i++)
        s += v[i].x * v[i].x + v[i].y * v[i].y + v[i].z * v[i].z + v[i].w * v[i].w;
#pragma unroll
    for (int i = 0; i < 3; i++) {
        __half2 p0 = __float22half2_rn(make_float2(v[2*i].x,   v[2*i].y));
        __half2 p1 = __float22half2_rn(make_float2(v[2*i].z,   v[2*i].w));
        __half2 p2 = __float22half2_rn(make_float2(v[2*i+1].x, v[2*i+1].y));
        __half2 p3 = __float22half2_rn(make_float2(v[2*i+1].z, v[2*i+1].w));
        uint4 w;
        w.x = *(u32*)&p0; w.y = *(u32*)&p1;
        w.z = *(u32*)&p2; w.w = *(u32*)&p3;
        orow[tid + 256 * i] = w;
    }

    __shared__ float red[256];
    red[tid] = s;
    __syncthreads();
    for (int o = 128; o; o >>= 1) {
        if (tid < o) red[tid] += red[tid + o];
        __syncthreads();
    }
    if (tid == 0) g_S2[t] = red[0];
}

// ---------------------------------------------------------------------------
// Kernel 1b: prefix sums of S2 (one block, double precision)
// ---------------------------------------------------------------------------
__global__ void __launch_bounds__(1024) prefix_kernel() {
    __shared__ double sm[1024];
    const int tid = threadIdx.x;
    double v[4], s = 0.0;
#pragma unroll
    for (int i = 0; i < 4; i++) { v[i] = (double)g_S2[4 * tid + i]; s += v[i]; }
    sm[tid] = s;
    __syncthreads();
    for (int off = 1; off < 1024; off <<= 1) {
        double tv = (tid >= off) ? sm[tid - off] : 0.0;
        __syncthreads();
        sm[tid] += tv;
        __syncthreads();
    }
    double run = tid ? sm[tid - 1] : 0.0;
    if (tid == 0) g_pref[0] = 0.0;
#pragma unroll
    for (int i = 0; i < 4; i++) { run += v[i]; g_pref[4 * tid + i + 1] = run; }
}

// ---------------------------------------------------------------------------
// Kernel 2: banded Gram matrix via mma.sync f16 (HMMA, f16 accumulate).
// ---------------------------------------------------------------------------
__device__ __forceinline__ void load_chunk(u32 stage, int kbase,
                                           int brow, int arow, int tid) {
    const __half* xp = g_xh + kbase;
#pragma unroll
    for (int it = 0; it < 8; it++) {
        int p = tid + it * 256;
        int t = p >> 10;                  // 0 = A (shift rows), 1 = B (base)
        int r = (p >> 3) & 127;
        int u = p & 7;
        int grow = (t ? brow : arow) + r;
        const void* src = xp + (size_t)grow * D_DIM + (u << 3);
        u32 dst = stage + (t << 14) +
                  (((u32)(r * 128 + u * 16)) ^ (((u32)(r & 7)) << 4));
        asm volatile("cp.async.cg.shared.global [%0], [%1], 16;"
                     :: "r"(dst), "l"(src) : "memory");
    }
}

__global__ void __launch_bounds__(256, 2) corr_kernel() {
    extern __shared__ __align__(1024) char smem[];
    const u32 sb = smem_u32(smem);
    const int tid = threadIdx.x, l = tid & 31, wid = tid >> 5;
    const int warp_m = wid >> 2, warp_n = wid & 3;
    const int n0 = blockIdx.x, qq = blockIdx.y, z = blockIdx.z;
    const int brow = n0 << 7;
    const int arow = (n0 + qq) << 7;
    const int kbase = z * KSPLIT;

    // Fragment usefulness mask (bit mi*4+ni). Interior: all 16.
    unsigned mask = 0xFFFFu;
    if (qq == 0 || qq == 8) {
        mask = 0;
#pragma unroll
        for (int mi = 0; mi < 4; mi++)
#pragma unroll
            for (int ni = 0; ni < 4; ni++) {
                int r0 = warp_m * 64 + mi * 16;
                int c0 = warp_n * 32 + ni * 8;
                bool used = (qq == 0) ? (r0 + 15 > c0)
                                      : (c0 + 7 > r0);
                if (used) mask |= 1u << (mi * 4 + ni);
            }
    }

    u32 c[4][4][2];
#pragma unroll
    for (int i = 0; i < 4; i++)
#pragma unroll
        for (int j = 0; j < 4; j++)
            c[i][j][0] = c[i][j][1] = 0u;

    const int a_row = warp_m * 64 + ((l >> 3) & 1) * 8 + (l & 7);
    const u32 a_off = (u32)(a_row * 128 + (l >> 4) * 16);
    const u32 a_swz = ((u32)(a_row & 7)) << 4;
    const int b_row = warp_n * 32 + (l & 7);
    const u32 b_off = (u32)(b_row * 128 + (l >> 3) * 16);
    const u32 b_swz = ((u32)(b_row & 7)) << 4;

    for (int s = 0; s < 2; s++) {
        load_chunk(sb + s * STAGE_B, kbase + s * KCH, brow, arow, tid);
        CP_COMMIT();
    }

    int sidx = 0;
    for (int ch = 0; ch < NCHUNK; ch++) {
        CP_WAIT(1);
        __syncthreads();
        if (mask) {
            const u32 Ab = sb + sidx * STAGE_B + a_off;
            const u32 Bb = sb + sidx * STAGE_B + TILE_B + b_off;
#pragma unroll
            for (int kd = 0; kd < 2; kd++) {
                u32 bq[4][4];
#pragma unroll
                for (int ni = 0; ni < 4; ni++)
                    LDSM4(bq[ni], (Bb + ni * 1024 + kd * 64) ^ b_swz);
#pragma unroll
                for (int h = 0; h < 2; h++) {
                    u32 aq[4][4];
#pragma unroll
                    for (int mi = 0; mi < 4; mi++)
                        LDSM4(aq[mi], (Ab + mi * 2048 + (kd * 2 + h) * 32) ^ a_swz);
                    if (mask == 0xFFFFu) {
#pragma unroll
                        for (int mi = 0; mi < 4; mi++)
#pragma unroll
                            for (int ni = 0; ni < 4; ni++)
                                MMAF16(c[mi][ni], aq[mi],
                                       bq[ni][2 * h], bq[ni][2 * h + 1]);
                    } else {
#pragma unroll
                        for (int mi = 0; mi < 4; mi++)
#pragma unroll
                            for (int ni = 0; ni < 4; ni++)
                                if (mask & (1u << (mi * 4 + ni)))
                                    MMAF16(c[mi][ni], aq[mi],
                                           bq[ni][2 * h], bq[ni][2 * h + 1]);
                    }
                }
            }
        }
        int cn = ch + 2;
        if (cn < NCHUNK) {
            int sn = sidx + 2; if (sn >= NST) sn -= NST;
            load_chunk(sb + sn * STAGE_B, kbase + cn * KCH, brow, arow, tid);
        }
        CP_COMMIT();
        if (++sidx == NST) sidx = 0;
    }

    // Epilogue: f16x2 regs -> float -> smem G (pitch 129) -> diagonal sums
    __syncthreads();
    float* G = (float*)smem;
#pragma unroll
    for (int mi = 0; mi < 4; mi++)
#pragma unroll
        for (int ni = 0; ni < 4; ni++) {
            int r0 = warp_m * 64 + mi * 16 + (l >> 2);
            int c0 = warp_n * 32 + ni * 8 + ((l & 3) << 1);
            float2 f0 = __half22float2(*(__half2*)&c[mi][ni][0]);
            float2 f1 = __half22float2(*(__half2*)&c[mi][ni][1]);
            G[r0 * 129 + c0]           = f0.x;
            G[r0 * 129 + c0 + 1]       = f0.y;
            G[(r0 + 8) * 129 + c0]     = f1.x;
            G[(r0 + 8) * 129 + c0 + 1] = f1.y;
        }
    __syncthreads();

    if (tid < 255) {
        int d = tid - 127;              // td = 128*qq + d
        float s = 0.f;
        for (int rr = 0; rr < 128; rr++) {
            int cc = rr - d;
            if ((unsigned)cc < 128u) s += G[rr * 129 + cc];
        }
        g_diag[((size_t)(z * NTILE + n0 * NQQ + qq)) * 256 + tid] = s;
    }
}

// ---------------------------------------------------------------------------
// Kernel 3: finalize, one warp per td. 128 blocks x 256 threads.
// msd[td] = (A[td] + A[0] - 2*C[td]) / (NT0*D), A from prefix sums.
// ---------------------------------------------------------------------------
__global__ void __launch_bounds__(256) finalize_kernel(float* __restrict__ out) {
    const int tid = threadIdx.x, l = tid & 31, w = tid >> 5;
    const int td = blockIdx.x * 8 + w;
    const int qq = td >> 7, d1 = td & 127;

    // 96 partials (NN0*NZ) spread over 32 lanes, 3 each.
    double cacc = 0.0;
#pragma unroll
    for (int it = 0; it < 3; it++) {
        int j = l + it * 32;            // j in [0,96)
        int n = j >> 2, zz = j & 3;
        double v = (double)g_diag[((size_t)(zz * NTILE + n * NQQ + qq)) * 256
                                  + 127 + d1];
        if (d1)
            v += (double)g_diag[((size_t)(zz * NTILE + n * NQQ + qq + 1)) * 256
                                + d1 - 1];
        cacc += v;
    }
#pragma unroll
    for (int o = 16; o; o >>= 1)
        cacc += __shfl_down_sync(0xFFFFFFFFu, cacc, o);

    if (l == 0) {
        double a  = g_pref[td + NT0] - g_pref[td];
        double a0 = g_pref[NT0];
        const double invN = 1.0 / ((double)NT0 * (double)D_DIM);
        out[td] = (td == 0) ? 0.0f
                            : (float)((a + a0 - 2.0 * cacc) * invN);
    }
}

// ---------------------------------------------------------------------------
extern "C" void kernel_launch(void* const* d_in, const int* in_sizes, int n_in,
                              void* d_out, int out_size) {
    (void)in_sizes; (void)n_in; (void)out_size;
    const float* x = (const float*)d_in[0];
    float* out = (float*)d_out;

    static bool attr_set = false;
    if (!attr_set) {
        cudaFuncSetAttribute(corr_kernel,
                             cudaFuncAttributeMaxDynamicSharedMemorySize,
                             SMEM_DYN);
        attr_set = true;
    }

    s2cvt_kernel<<<T_DIM, 256>>>(x);
    prefix_kernel<<<1, 1024>>>();
    corr_kernel<<<dim3(NN0, NQQ, NZ), 256, SMEM_DYN>>>();
    finalize_kernel<<<TDM / 8, 256>>>(out);
}

// round 16
// speedup vs baseline: 2.3175x; 1.0222x over previous
#include <cuda_runtime.h>
#include <cuda_fp16.h>
#include <cstdint>

// ---------------- geometry ----------------
#define T_DIM   4096
#define D_DIM   6144
#define NT0     3072
#define TDM     1024

// ---------------- tiling ------------------
#define KCH     64                   // f16 K per chunk (128B row)
#define NZ      4                    // K splits
#define KSPLIT  (D_DIM/NZ)           // 1536
#define NCHUNK  (KSPLIT/KCH)         // 24 chunks per K-quarter
#define NST     3                    // pipeline stages
#define TILE_B  16384                // 128 rows x 128 B
#define STAGE_B (2*TILE_B)           // A(shift) + B(base)
#define SMEM_DYN (NST*STAGE_B)       // 98304
#define NN0     24
#define NQQ     9
#define NTILE   (NN0*NQQ)            // 216

typedef unsigned int u32;

// ---------------- scratch (device globals) --------------
__device__ __half g_xh[(size_t)T_DIM * D_DIM];           // 48 MB fp16 copy
__device__ float g_S2[T_DIM];
__device__ float g_diag[NZ * NTILE * 256];

// ---------------- PTX helpers ----------------
__device__ __forceinline__ u32 smem_u32(const void* p) {
    u32 a;
    asm("{ .reg .u64 t; cvta.to.shared.u64 t, %1; cvt.u32.u64 %0, t; }"
        : "=r"(a) : "l"(p));
    return a;
}
#define CP_COMMIT()  asm volatile("cp.async.commit_group;" ::: "memory")
#define CP_WAIT(n)   asm volatile("cp.async.wait_group %0;" :: "n"(n) : "memory")

#define LDSM4(r, addr) \
    asm volatile("ldmatrix.sync.aligned.m8n8.x4.shared.b16 {%0,%1,%2,%3}, [%4];" \
        : "=r"((r)[0]), "=r"((r)[1]), "=r"((r)[2]), "=r"((r)[3]) : "r"(addr))

// fp16 inputs, fp16 accumulate, C = two b32 regs (f16x2)
#define MMAF16(c, a, b0, b1) \
    asm volatile("mma.sync.aligned.m16n8k16.row.col.f16.f16.f16.f16 " \
        "{%0,%1}, {%2,%3,%4,%5}, {%6,%7}, {%0,%1};" \
        : "+r"((c)[0]), "+r"((c)[1]) \
        : "r"((a)[0]), "r"((a)[1]), "r"((a)[2]), "r"((a)[3]), "r"(b0), "r"(b1))

// ---------------------------------------------------------------------------
// Kernel 1: fp32 -> fp16 convert + exact per-row sum of squares.
// ---------------------------------------------------------------------------
__global__ void __launch_bounds__(256) s2cvt_kernel(const float* __restrict__ x) {
    int t = blockIdx.x;
    const float4* row = (const float4*)(x + (size_t)t * D_DIM);
    uint4* orow = (uint4*)(g_xh + (size_t)t * D_DIM);
    const int tid = threadIdx.x;

    float4 v[6];
#pragma unroll
    for (int i = 0; i < 3; i++) {
        v[2 * i]     = row[2 * tid + 512 * i];
        v[2 * i + 1] = row[2 * tid + 512 * i + 1];
    }
    float s = 0.f;
#pragma unroll
    for (int i = 0; i < 6; i++)
        s += v[i].x * v[i].x + v[i].y * v[i].y + v[i].z * v[i].z + v[i].w * v[i].w;
#pragma unroll
    for (int i = 0; i < 3; i++) {
        __half2 p0 = __float22half2_rn(make_float2(v[2*i].x,   v[2*i].y));
        __half2 p1 = __float22half2_rn(make_float2(v[2*i].z,   v[2*i].w));
        __half2 p2 = __float22half2_rn(make_float2(v[2*i+1].x, v[2*i+1].y));
        __half2 p3 = __float22half2_rn(make_float2(v[2*i+1].z, v[2*i+1].w));
        uint4 w;
        w.x = *(u32*)&p0; w.y = *(u32*)&p1;
        w.z = *(u32*)&p2; w.w = *(u32*)&p3;
        orow[tid + 256 * i] = w;
    }

    __shared__ float red[256];
    red[tid] = s;
    __syncthreads();
    for (int o = 128; o; o >>= 1) {
        if (tid < o) red[tid] += red[tid + o];
        __syncthreads();
    }
    if (tid == 0) g_S2[t] = red[0];
}

// ---------------------------------------------------------------------------
// Kernel 2: banded Gram matrix via mma.sync f16 (HMMA, f16 accumulate).
// ---------------------------------------------------------------------------
__device__ __forceinline__ void load_chunk(u32 stage, int kbase,
                                           int brow, int arow, int tid) {
    const __half* xp = g_xh + kbase;
#pragma unroll
    for (int it = 0; it < 8; it++) {
        int p = tid + it * 256;
        int t = p >> 10;                  // 0 = A (shift rows), 1 = B (base)
        int r = (p >> 3) & 127;
        int u = p & 7;
        int grow = (t ? brow : arow) + r;
        const void* src = xp + (size_t)grow * D_DIM + (u << 3);
        u32 dst = stage + (t << 14) +
                  (((u32)(r * 128 + u * 16)) ^ (((u32)(r & 7)) << 4));
        asm volatile("cp.async.cg.shared.global [%0], [%1], 16;"
                     :: "r"(dst), "l"(src) : "memory");
    }
}

__global__ void __launch_bounds__(256, 2) corr_kernel() {
    extern __shared__ __align__(1024) char smem[];
    const u32 sb = smem_u32(smem);
    const int tid = threadIdx.x, l = tid & 31, wid = tid >> 5;
    const int warp_m = wid >> 2, warp_n = wid & 3;
    const int n0 = blockIdx.x, qq = blockIdx.y, z = blockIdx.z;
    const int brow = n0 << 7;
    const int arow = (n0 + qq) << 7;
    const int kbase = z * KSPLIT;

    // Fragment usefulness mask (bit mi*4+ni). Interior: all 16.
    unsigned mask = 0xFFFFu;
    if (qq == 0 || qq == 8) {
        mask = 0;
#pragma unroll
        for (int mi = 0; mi < 4; mi++)
#pragma unroll
            for (int ni = 0; ni < 4; ni++) {
                int r0 = warp_m * 64 + mi * 16;
                int c0 = warp_n * 32 + ni * 8;
                bool used = (qq == 0) ? (r0 + 15 > c0)
                                      : (c0 + 7 > r0);
                if (used) mask |= 1u << (mi * 4 + ni);
            }
    }

    u32 c[4][4][2];
#pragma unroll
    for (int i = 0; i < 4; i++)
#pragma unroll
        for (int j = 0; j < 4; j++)
            c[i][j][0] = c[i][j][1] = 0u;

    const int a_row = warp_m * 64 + ((l >> 3) & 1) * 8 + (l & 7);
    const u32 a_off = (u32)(a_row * 128 + (l >> 4) * 16);
    const u32 a_swz = ((u32)(a_row & 7)) << 4;
    const int b_row = warp_n * 32 + (l & 7);
    const u32 b_off = (u32)(b_row * 128 + (l >> 3) * 16);
    const u32 b_swz = ((u32)(b_row & 7)) << 4;

    for (int s = 0; s < 2; s++) {
        load_chunk(sb + s * STAGE_B, kbase + s * KCH, brow, arow, tid);
        CP_COMMIT();
    }

    int sidx = 0;
    for (int ch = 0; ch < NCHUNK; ch++) {
        CP_WAIT(1);
        __syncthreads();
        if (mask) {
            const u32 Ab = sb + sidx * STAGE_B + a_off;
            const u32 Bb = sb + sidx * STAGE_B + TILE_B + b_off;
#pragma unroll
            for (int kd = 0; kd < 2; kd++) {
                u32 bq[4][4];
#pragma unroll
                for (int ni = 0; ni < 4; ni++)
                    LDSM4(bq[ni], (Bb + ni * 1024 + kd * 64) ^ b_swz);
#pragma unroll
                for (int h = 0; h < 2; h++) {
                    u32 aq[4][4];
#pragma unroll
                    for (int mi = 0; mi < 4; mi++)
                        LDSM4(aq[mi], (Ab + mi * 2048 + (kd * 2 + h) * 32) ^ a_swz);
                    if (mask == 0xFFFFu) {
#pragma unroll
                        for (int mi = 0; mi < 4; mi++)
#pragma unroll
                            for (int ni = 0; ni < 4; ni++)
                                MMAF16(c[mi][ni], aq[mi],
                                       bq[ni][2 * h], bq[ni][2 * h + 1]);
                    } else {
#pragma unroll
                        for (int mi = 0; mi < 4; mi++)
#pragma unroll
                            for (int ni = 0; ni < 4; ni++)
                                if (mask & (1u << (mi * 4 + ni)))
                                    MMAF16(c[mi][ni], aq[mi],
                                           bq[ni][2 * h], bq[ni][2 * h + 1]);
                    }
                }
            }
        }
        int cn = ch + 2;
        if (cn < NCHUNK) {
            int sn = sidx + 2; if (sn >= NST) sn -= NST;
            load_chunk(sb + sn * STAGE_B, kbase + cn * KCH, brow, arow, tid);
        }
        CP_COMMIT();
        if (++sidx == NST) sidx = 0;
    }

    // Epilogue: f16x2 regs -> float -> smem G (pitch 129) -> diagonal sums
    __syncthreads();
    float* G = (float*)smem;
#pragma unroll
    for (int mi = 0; mi < 4; mi++)
#pragma unroll
        for (int ni = 0; ni < 4; ni++) {
            int r0 = warp_m * 64 + mi * 16 + (l >> 2);
            int c0 = warp_n * 32 + ni * 8 + ((l & 3) << 1);
            float2 f0 = __half22float2(*(__half2*)&c[mi][ni][0]);
            float2 f1 = __half22float2(*(__half2*)&c[mi][ni][1]);
            G[r0 * 129 + c0]           = f0.x;
            G[r0 * 129 + c0 + 1]       = f0.y;
            G[(r0 + 8) * 129 + c0]     = f1.x;
            G[(r0 + 8) * 129 + c0 + 1] = f1.y;
        }
    __syncthreads();

    if (tid < 255) {
        int d = tid - 127;              // td = 128*qq + d
        float s = 0.f;
        for (int rr = 0; rr < 128; rr++) {
            int cc = rr - d;
            if ((unsigned)cc < 128u) s += G[rr * 129 + cc];
        }
        g_diag[((size_t)(z * NTILE + n0 * NQQ + qq)) * 256 + tid] = s;
    }
}

// ---------------------------------------------------------------------------
// Kernel 3: finalize (self-contained; no prefix kernel).
// Block b handles td = 8b..8b+7. Block computes W = sum S2[td0..td0+3071]
// and A0 = sum S2[0..3071] in fp64; warp w telescopes to td0+w and adds
// its C-partials via shuffle reduce.
// ---------------------------------------------------------------------------
__global__ void __launch_bounds__(256) finalize_kernel(float* __restrict__ out) {
    const int tid = threadIdx.x, l = tid & 31, w = tid >> 5;
    const int td0 = blockIdx.x * 8;

    // Block-wide window sums (fp64, deterministic tree).
    double sW = 0.0, s0 = 0.0;
#pragma unroll
    for (int i = 0; i < 12; i++) {
        int j = tid + 256 * i;          // j in [0,3072)
        sW += (double)g_S2[td0 + j];
        s0 += (double)g_S2[j];
    }
    __shared__ double redW[256], red0[256];
    redW[tid] = sW; red0[tid] = s0;
    __syncthreads();
    for (int o = 128; o; o >>= 1) {
        if (tid < o) { redW[tid] += redW[tid + o]; red0[tid] += red0[tid + o]; }
        __syncthreads();
    }
    const double W  = redW[0];          // A[td0]
    const double A0 = red0[0];

    // Per-warp telescoping correction: A[td0+w] = W + sum_{m<w}(S2[td0+3072+m]-S2[td0+m])
    double corr = 0.0;
    if (l < w)
        corr = (double)g_S2[td0 + NT0 + l] - (double)g_S2[td0 + l];
#pragma unroll
    for (int o = 4; o; o >>= 1)
        corr += __shfl_down_sync(0xFFFFFFFFu, corr, o);
    corr = __shfl_sync(0xFFFFFFFFu, corr, 0);

    // C[td]: 96 partials spread over 32 lanes, 3 each.
    const int td = td0 + w;
    const int qq = td >> 7, d1 = td & 127;
    double cacc = 0.0;
#pragma unroll
    for (int it = 0; it < 3; it++) {
        int j = l + it * 32;            // j in [0,96)
        int n = j >> 2, zz = j & 3;
        double v = (double)g_diag[((size_t)(zz * NTILE + n * NQQ + qq)) * 256
                                  + 127 + d1];
        if (d1)
            v += (double)g_diag[((size_t)(zz * NTILE + n * NQQ + qq + 1)) * 256
                                + d1 - 1];
        cacc += v;
    }
#pragma unroll
    for (int o = 16; o; o >>= 1)
        cacc += __shfl_down_sync(0xFFFFFFFFu, cacc, o);

    if (l == 0) {
        const double invN = 1.0 / ((double)NT0 * (double)D_DIM);
        out[td] = (td == 0) ? 0.0f
                            : (float)(((W + corr) + A0 - 2.0 * cacc) * invN);
    }
}

// ---------------------------------------------------------------------------
extern "C" void kernel_launch(void* const* d_in, const int* in_sizes, int n_in,
                              void* d_out, int out_size) {
    (void)in_sizes; (void)n_in; (void)out_size;
    const float* x = (const float*)d_in[0];
    float* out = (float*)d_out;

    static bool attr_set = false;
    if (!attr_set) {
        cudaFuncSetAttribute(corr_kernel,
                             cudaFuncAttributeMaxDynamicSharedMemorySize,
                             SMEM_DYN);
        attr_set = true;
    }

    s2cvt_kernel<<<T_DIM, 256>>>(x);
    corr_kernel<<<dim3(NN0, NQQ, NZ), 256, SMEM_DYN>>>();
    finalize_kernel<<<TDM / 8, 256>>>(out);
}

// round 17
// speedup vs baseline: 2.3848x; 1.0290x over previous
#include <cuda_runtime.h>
#include <cuda_fp16.h>
#include <cstdint>

// ---------------- geometry ----------------
#define T_DIM   4096
#define D_DIM   6144
#define NT0     3072
#define TDM     1024

// ---------------- tiling ------------------
#define KCH     64                   // f16 K per chunk (128B row)
#define NZ      4                    // K splits
#define KSPLIT  (D_DIM/NZ)           // 1536
#define NCHUNK  (KSPLIT/KCH)         // 24 chunks per K-quarter
#define NST     3                    // pipeline stages
#define TILE_B  16384                // 128 rows x 128 B
#define STAGE_B (2*TILE_B)           // A(shift) + B(base)
#define SMEM_DYN (NST*STAGE_B)       // 98304
#define NN0     24
#define NQQ     9
#define NTILE   (NN0*NQQ)            // 216

typedef unsigned int u32;

// ---------------- scratch (device globals) --------------
__device__ __half g_xh[(size_t)T_DIM * D_DIM];           // 48 MB fp16 copy
__device__ float g_S2[T_DIM];
__device__ float g_diag[NZ * NTILE * 256];

// ---------------- PTX helpers ----------------
__device__ __forceinline__ u32 smem_u32(const void* p) {
    u32 a;
    asm("{ .reg .u64 t; cvta.to.shared.u64 t, %1; cvt.u32.u64 %0, t; }"
        : "=r"(a) : "l"(p));
    return a;
}
#define CP_COMMIT()  asm volatile("cp.async.commit_group;" ::: "memory")
#define CP_WAIT(n)   asm volatile("cp.async.wait_group %0;" :: "n"(n) : "memory")

#define LDSM4(r, addr) \
    asm volatile("ldmatrix.sync.aligned.m8n8.x4.shared.b16 {%0,%1,%2,%3}, [%4];" \
        : "=r"((r)[0]), "=r"((r)[1]), "=r"((r)[2]), "=r"((r)[3]) : "r"(addr))

// fp16 inputs, fp16 accumulate, C = two b32 regs (f16x2)
#define MMAF16(c, a, b0, b1) \
    asm volatile("mma.sync.aligned.m16n8k16.row.col.f16.f16.f16.f16 " \
        "{%0,%1}, {%2,%3,%4,%5}, {%6,%7}, {%0,%1};" \
        : "+r"((c)[0]), "+r"((c)[1]) \
        : "r"((a)[0]), "r"((a)[1]), "r"((a)[2]), "r"((a)[3]), "r"(b0), "r"(b1))

// ---------------------------------------------------------------------------
// Kernel 1: fp32 -> fp16 convert + exact per-row sum of squares.
// 2 rows per block, 12 streaming (evict-first) float4 loads in flight.
// ---------------------------------------------------------------------------
__global__ void __launch_bounds__(256) s2cvt_kernel(const float* __restrict__ x) {
    const int tid = threadIdx.x;
    const int half = tid >> 7;                 // 0/1: which row of the pair
    const int lt = tid & 127;                  // lane within row-half
    const int t = blockIdx.x * 2 + half;

    const float4* row = (const float4*)(x + (size_t)t * D_DIM);
    uint4* orow = (uint4*)(g_xh + (size_t)t * D_DIM);

    // 12 streaming loads batched (x is read exactly once -> evict-first).
    float4 v[12];
#pragma unroll
    for (int i = 0; i < 6; i++) {
        v[2 * i]     = __ldcs(&row[2 * lt + 256 * i]);
        v[2 * i + 1] = __ldcs(&row[2 * lt + 256 * i + 1]);
    }
    float s = 0.f;
#pragma unroll
    for (int i = 0; i < 12; i++)
        s += v[i].x * v[i].x + v[i].y * v[i].y + v[i].z * v[i].z + v[i].w * v[i].w;
#pragma unroll
    for (int i = 0; i < 6; i++) {
        __half2 p0 = __float22half2_rn(make_float2(v[2*i].x,   v[2*i].y));
        __half2 p1 = __float22half2_rn(make_float2(v[2*i].z,   v[2*i].w));
        __half2 p2 = __float22half2_rn(make_float2(v[2*i+1].x, v[2*i+1].y));
        __half2 p3 = __float22half2_rn(make_float2(v[2*i+1].z, v[2*i+1].w));
        uint4 w;
        w.x = *(u32*)&p0; w.y = *(u32*)&p1;
        w.z = *(u32*)&p2; w.w = *(u32*)&p3;
        orow[lt + 128 * i] = w;
    }

    // Per-half reduction (two independent rows in one block).
    __shared__ float red[256];
    red[tid] = s;
    __syncthreads();
    for (int o = 64; o; o >>= 1) {
        if (lt < o) red[tid] += red[tid + o];
        __syncthreads();
    }
    if (lt == 0) g_S2[t] = red[half << 7];
}

// ---------------------------------------------------------------------------
// Kernel 2: banded Gram matrix via mma.sync f16 (HMMA, f16 accumulate).
// ---------------------------------------------------------------------------
__device__ __forceinline__ void load_chunk(u32 stage, int kbase,
                                           int brow, int arow, int tid) {
    const __half* xp = g_xh + kbase;
#pragma unroll
    for (int it = 0; it < 8; it++) {
        int p = tid + it * 256;
        int t = p >> 10;                  // 0 = A (shift rows), 1 = B (base)
        int r = (p >> 3) & 127;
        int u = p & 7;
        int grow = (t ? brow : arow) + r;
        const void* src = xp + (size_t)grow * D_DIM + (u << 3);
        u32 dst = stage + (t << 14) +
                  (((u32)(r * 128 + u * 16)) ^ (((u32)(r & 7)) << 4));
        asm volatile("cp.async.cg.shared.global [%0], [%1], 16;"
                     :: "r"(dst), "l"(src) : "memory");
    }
}

__global__ void __launch_bounds__(256, 2) corr_kernel() {
    extern __shared__ __align__(1024) char smem[];
    const u32 sb = smem_u32(smem);
    const int tid = threadIdx.x, l = tid & 31, wid = tid >> 5;
    const int warp_m = wid >> 2, warp_n = wid & 3;
    const int n0 = blockIdx.x, qq = blockIdx.y, z = blockIdx.z;
    const int brow = n0 << 7;
    const int arow = (n0 + qq) << 7;
    const int kbase = z * KSPLIT;

    // Fragment usefulness mask (bit mi*4+ni). Interior: all 16.
    unsigned mask = 0xFFFFu;
    if (qq == 0 || qq == 8) {
        mask = 0;
#pragma unroll
        for (int mi = 0; mi < 4; mi++)
#pragma unroll
            for (int ni = 0; ni < 4; ni++) {
                int r0 = warp_m * 64 + mi * 16;
                int c0 = warp_n * 32 + ni * 8;
                bool used = (qq == 0) ? (r0 + 15 > c0)
                                      : (c0 + 7 > r0);
                if (used) mask |= 1u << (mi * 4 + ni);
            }
    }

    u32 c[4][4][2];
#pragma unroll
    for (int i = 0; i < 4; i++)
#pragma unroll
        for (int j = 0; j < 4; j++)
            c[i][j][0] = c[i][j][1] = 0u;

    const int a_row = warp_m * 64 + ((l >> 3) & 1) * 8 + (l & 7);
    const u32 a_off = (u32)(a_row * 128 + (l >> 4) * 16);
    const u32 a_swz = ((u32)(a_row & 7)) << 4;
    const int b_row = warp_n * 32 + (l & 7);
    const u32 b_off = (u32)(b_row * 128 + (l >> 3) * 16);
    const u32 b_swz = ((u32)(b_row & 7)) << 4;

    for (int s = 0; s < 2; s++) {
        load_chunk(sb + s * STAGE_B, kbase + s * KCH, brow, arow, tid);
        CP_COMMIT();
    }

    int sidx = 0;
    for (int ch = 0; ch < NCHUNK; ch++) {
        CP_WAIT(1);
        __syncthreads();
        if (mask) {
            const u32 Ab = sb + sidx * STAGE_B + a_off;
            const u32 Bb = sb + sidx * STAGE_B + TILE_B + b_off;
#pragma unroll
            for (int kd = 0; kd < 2; kd++) {
                u32 bq[4][4];
#pragma unroll
                for (int ni = 0; ni < 4; ni++)
                    LDSM4(bq[ni], (Bb + ni * 1024 + kd * 64) ^ b_swz);
#pragma unroll
                for (int h = 0; h < 2; h++) {
                    u32 aq[4][4];
#pragma unroll
                    for (int mi = 0; mi < 4; mi++)
                        LDSM4(aq[mi], (Ab + mi * 2048 + (kd * 2 + h) * 32) ^ a_swz);
                    if (mask == 0xFFFFu) {
#pragma unroll
                        for (int mi = 0; mi < 4; mi++)
#pragma unroll
                            for (int ni = 0; ni < 4; ni++)
                                MMAF16(c[mi][ni], aq[mi],
                                       bq[ni][2 * h], bq[ni][2 * h + 1]);
                    } else {
#pragma unroll
                        for (int mi = 0; mi < 4; mi++)
#pragma unroll
                            for (int ni = 0; ni < 4; ni++)
                                if (mask & (1u << (mi * 4 + ni)))
                                    MMAF16(c[mi][ni], aq[mi],
                                           bq[ni][2 * h], bq[ni][2 * h + 1]);
                    }
                }
            }
        }
        int cn = ch + 2;
        if (cn < NCHUNK) {
            int sn = sidx + 2; if (sn >= NST) sn -= NST;
            load_chunk(sb + sn * STAGE_B, kbase + cn * KCH, brow, arow, tid);
        }
        CP_COMMIT();
        if (++sidx == NST) sidx = 0;
    }

    // Epilogue: f16x2 regs -> float -> smem G (pitch 129) -> diagonal sums
    __syncthreads();
    float* G = (float*)smem;
#pragma unroll
    for (int mi = 0; mi < 4; mi++)
#pragma unroll
        for (int ni = 0; ni < 4; ni++) {
            int r0 = warp_m * 64 + mi * 16 + (l >> 2);
            int c0 = warp_n * 32 + ni * 8 + ((l & 3) << 1);
            float2 f0 = __half22float2(*(__half2*)&c[mi][ni][0]);
            float2 f1 = __half22float2(*(__half2*)&c[mi][ni][1]);
            G[r0 * 129 + c0]           = f0.x;
            G[r0 * 129 + c0 + 1]       = f0.y;
            G[(r0 + 8) * 129 + c0]     = f1.x;
            G[(r0 + 8) * 129 + c0 + 1] = f1.y;
        }
    __syncthreads();

    if (tid < 255) {
        int d = tid - 127;              // td = 128*qq + d
        float s = 0.f;
        for (int rr = 0; rr < 128; rr++) {
            int cc = rr - d;
            if ((unsigned)cc < 128u) s += G[rr * 129 + cc];
        }
        g_diag[((size_t)(z * NTILE + n0 * NQQ + qq)) * 256 + tid] = s;
    }
}

// ---------------------------------------------------------------------------
// Kernel 3: finalize (self-contained).
// Block b handles td = 8b..8b+7; W and A0 via block fp64 tree, per-warp
// telescoping to td0+w, C-partials via shuffle reduce.
// ---------------------------------------------------------------------------
__global__ void __launch_bounds__(256) finalize_kernel(float* __restrict__ out) {
    const int tid = threadIdx.x, l = tid & 31, w = tid >> 5;
    const int td0 = blockIdx.x * 8;

    double sW = 0.0, s0 = 0.0;
#pragma unroll
    for (int i = 0; i < 12; i++) {
        int j = tid + 256 * i;          // j in [0,3072)
        sW += (double)g_S2[td0 + j];
        s0 += (double)g_S2[j];
    }
    __shared__ double redW[256], red0[256];
    redW[tid] = sW; red0[tid] = s0;
    __syncthreads();
    for (int o = 128; o; o >>= 1) {
        if (tid < o) { redW[tid] += redW[tid + o]; red0[tid] += red0[tid + o]; }
        __syncthreads();
    }
    const double W  = redW[0];          // A[td0]
    const double A0 = red0[0];

    double corr = 0.0;
    if (l < w)
        corr = (double)g_S2[td0 + NT0 + l] - (double)g_S2[td0 + l];
#pragma unroll
    for (int o = 4; o; o >>= 1)
        corr += __shfl_down_sync(0xFFFFFFFFu, corr, o);
    corr = __shfl_sync(0xFFFFFFFFu, corr, 0);

    const int td = td0 + w;
    const int qq = td >> 7, d1 = td & 127;
    double cacc = 0.0;
#pragma unroll
    for (int it = 0; it < 3; it++) {
        int j = l + it * 32;            // j in [0,96)
        int n = j >> 2, zz = j & 3;
        double v = (double)g_diag[((size_t)(zz * NTILE + n * NQQ + qq)) * 256
                                  + 127 + d1];
        if (d1)
            v += (double)g_diag[((size_t)(zz * NTILE + n * NQQ + qq + 1)) * 256
                                + d1 - 1];
        cacc += v;
    }
#pragma unroll
    for (int o = 16; o; o >>= 1)
        cacc += __shfl_down_sync(0xFFFFFFFFu, cacc, o);

    if (l == 0) {
        const double invN = 1.0 / ((double)NT0 * (double)D_DIM);
        out[td] = (td == 0) ? 0.0f
                            : (float)(((W + corr) + A0 - 2.0 * cacc) * invN);
    }
}

// ---------------------------------------------------------------------------
extern "C" void kernel_launch(void* const* d_in, const int* in_sizes, int n_in,
                              void* d_out, int out_size) {
    (void)in_sizes; (void)n_in; (void)out_size;
    const float* x = (const float*)d_in[0];
    float* out = (float*)d_out;

    static bool attr_set = false;
    if (!attr_set) {
        cudaFuncSetAttribute(corr_kernel,
                             cudaFuncAttributeMaxDynamicSharedMemorySize,
                             SMEM_DYN);
        attr_set = true;
    }

    s2cvt_kernel<<<T_DIM / 2, 256>>>(x);
    corr_kernel<<<dim3(NN0, NQQ, NZ), 256, SMEM_DYN>>>();
    finalize_kernel<<<TDM / 8, 256>>>(out);
}